// round 12
// baseline (speedup 1.0000x reference)
#include <cuda_runtime.h>
#include <cstdint>

// IFS trajectory — BLOCK=256, 3 blocks/SM, TILE=16, depth-2 cp.async (NBUF=3).
// inputs: d_in[0] = coef (BATCH, 12) f32, d_in[1] = h (ITERS, BATCH) f32
// output: (BATCH, ITERS+1, 2) f32
//
// Column tiling: tile t owns output cols [16t,16t+16); col c>0 consumes h[c-1],
// col 0 = initial point (folded into tile 0). Tile t's h rows: 16t-1+row.
//
// Ring discipline (fixes R11 race): per tile t the order is
//   cp_wait<1>  ->  __syncthreads  ->  prefetch(t+2)  ->  compute -> flush
// prefetch(t+2) overwrites slot (t-1)%3 strictly AFTER barrier #t, and all
// reads of tile t-1 happen before barrier #t, so the overwrite cannot race.
// Prefetch distance is still 2 tile-periods (t+2 issued at start of iter t).
//
// Staging: 8-step per-warp-column buffer, flushed twice per tile (__syncwarp).
// Flush: quarter-warp writes one row's 8 float2 = 64B contiguous.

#define BLOCK 256
#define TILE  16
#define HTILE 8
#define NBUF  3
#define SOROW (BLOCK + 2)

__device__ __forceinline__ void cp_async16(uint32_t saddr, const void* gptr) {
    asm volatile("cp.async.cg.shared.global [%0], [%1], 16;\n"
                 :: "r"(saddr), "l"(gptr));
}
__device__ __forceinline__ void cp_commit() {
    asm volatile("cp.async.commit_group;\n");
}
template <int N>
__device__ __forceinline__ void cp_wait() {
    asm volatile("cp.async.wait_group %0;\n" :: "n"(N));
}

template <int BATCH_C, int ITERS_C>
__global__ __launch_bounds__(BLOCK, 3) void ifs_spec(
    const float* __restrict__ coef,
    const float* __restrict__ h,
    float2* __restrict__ out)
{
    constexpr int STRIDE = ITERS_C + 1;             // 101
    constexpr int NTILE  = STRIDE / TILE;           // 6  (cols 0..95)
    constexpr int TREM   = STRIDE - NTILE * TILE;   // 5  (cols 96..100)

    __shared__ __align__(16) float sh[NBUF][TILE][BLOCK];  // 48 KB
    __shared__ float2 so[HTILE][SOROW];                     // ~16.1 KB

    const int tid  = threadIdx.x;
    const int block_b0 = blockIdx.x * BLOCK;

    // ---------------- partial last block: simple per-thread path -----------
    if (block_b0 + BLOCK > BATCH_C) {
        const int b = block_b0 + tid;
        if (b >= BATCH_C) return;
        const float4* c4 = reinterpret_cast<const float4*>(coef + (size_t)b * 12);
        float4 ca = c4[0], cb = c4[1], cc = c4[2];
        float A0=ca.x, A1=ca.y, A2=ca.z, A3=ca.w, A4=cb.x, A5=cb.y;
        float B0=cb.z, B1=cb.w, B2=cc.x, B3=cc.y, B4=cc.z, B5=cc.w;
        float j0 = fabsf(A0*A3 - A1*A2);
        float j1 = fabsf(B0*B3 - B1*B2);
        float p = j0 / (j0 + j1);
        float x = 0.05f, y = 0.05f;
        float2* o = out + (size_t)b * STRIDE;
        o[0] = make_float2(x, y);
        #pragma unroll 4
        for (int t = 0; t < ITERS_C; ++t) {
            float ht = __ldg(h + (size_t)t * BATCH_C + b);
            bool m = ht > p;
            float xn = fmaf(m?B0:A0, x, fmaf(m?B1:A1, y, m?B4:A4));
            float yn = fmaf(m?B2:A2, x, fmaf(m?B3:A3, y, m?B5:A5));
            x = xn; y = yn;
            o[t + 1] = make_float2(x, y);
        }
        return;
    }

    // ---------------- full blocks: checkless fast path ----------------------
    const int warp = tid >> 5;
    const int lane = tid & 31;

    float A0,A1,A2,A3,A4,A5,B0,B1,B2,B3,B4,B5,p;
    {
        const int b = block_b0 + tid;
        const float4* c4 = reinterpret_cast<const float4*>(coef + (size_t)b * 12);
        float4 ca = c4[0], cb = c4[1], cc = c4[2];
        A0=ca.x; A1=ca.y; A2=ca.z; A3=ca.w; A4=cb.x; A5=cb.y;
        B0=cb.z; B1=cb.w; B2=cc.x; B3=cc.y; B4=cc.z; B5=cc.w;
        float j0 = fabsf(A0*A3 - A1*A2);
        float j1 = fabsf(B0*B3 - B1*B2);
        p = j0 / (j0 + j1);
    }
    float x = 0.05f, y = 0.05f;

    // ---- prefetch: tile = 16 rows x 256 floats = 1024 x 16B chunks, 4/thread
    const uint32_t sh_base = (uint32_t)__cvta_generic_to_shared(&sh[0][0][0]);
    auto prefetch = [&](int tile) {
        if (tile < NTILE) {
            const int buf = tile % NBUF;
            #pragma unroll
            for (int i = 0; i < 4; ++i) {
                const int flat = tid + i * BLOCK;     // 0..1023
                const int row  = flat >> 6;           // 0..15 (64 chunks/row)
                const int c4   = (flat & 63) << 2;    // float col 0..252
                const int rg   = tile * TILE - 1 + row;
                if (rg >= 0)                           // only tile 0, row 0 skips
                    cp_async16(sh_base +
                               (uint32_t)(((buf * TILE + row) * BLOCK + c4) << 2),
                               h + (size_t)rg * BATCH_C + block_b0 + c4);
            }
        }
        cp_commit();
    };

    prefetch(0);
    prefetch(1);

    const int q   = lane >> 3;          // quarter-warp group 0..3
    const int ttf = lane & 7;           // time index for flush
    const int wcol = warp * 32 + q;     // staging column base for this lane

    // flush staged half-tile: quarter-warp writes one row's 8 float2 = 64B
    auto flush = [&](int col0) {        // col0 = first global output column
        float2* obase = out + (size_t)(block_b0 + wcol) * STRIDE + col0 + ttf;
        #pragma unroll
        for (int k = 0; k < 8; ++k)
            obase[(size_t)(4 * k) * STRIDE] = so[ttf][wcol + 4 * k];
    };

    for (int tile = 0; tile < NTILE; ++tile) {
        cp_wait<1>();                    // tile t's group complete (only t+1 newer)
        __syncthreads();                 // h tile visible; reads of t-1 all done
        prefetch(tile + 2);              // safe: overwrites slot (t-1)%3 post-barrier

        const int buf = tile % NBUF;

        // ---- first half: cols [16t, 16t+8) ----
        if (tile == 0) {
            so[0][tid] = make_float2(0.05f, 0.05f);
            #pragma unroll
            for (int j = 1; j < HTILE; ++j) {
                float ht = sh[buf][j][tid];
                float xA = fmaf(A0, x, fmaf(A1, y, A4));
                float yA = fmaf(A2, x, fmaf(A3, y, A5));
                float xB = fmaf(B0, x, fmaf(B1, y, B4));
                float yB = fmaf(B2, x, fmaf(B3, y, B5));
                bool m = ht > p;
                x = m ? xB : xA;
                y = m ? yB : yA;
                so[j][tid] = make_float2(x, y);
            }
        } else {
            #pragma unroll
            for (int j = 0; j < HTILE; ++j) {
                float ht = sh[buf][j][tid];
                float xA = fmaf(A0, x, fmaf(A1, y, A4));
                float yA = fmaf(A2, x, fmaf(A3, y, A5));
                float xB = fmaf(B0, x, fmaf(B1, y, B4));
                float yB = fmaf(B2, x, fmaf(B3, y, B5));
                bool m = ht > p;
                x = m ? xB : xA;
                y = m ? yB : yA;
                so[j][tid] = make_float2(x, y);
            }
        }
        __syncwarp();
        flush(tile * TILE);
        __syncwarp();                    // staging reusable within warp

        // ---- second half: cols [16t+8, 16t+16) ----
        #pragma unroll
        for (int j = 0; j < HTILE; ++j) {
            float ht = sh[buf][HTILE + j][tid];
            float xA = fmaf(A0, x, fmaf(A1, y, A4));
            float yA = fmaf(A2, x, fmaf(A3, y, A5));
            float xB = fmaf(B0, x, fmaf(B1, y, B4));
            float yB = fmaf(B2, x, fmaf(B3, y, B5));
            bool m = ht > p;
            x = m ? xB : xA;
            y = m ? yB : yA;
            so[j][tid] = make_float2(x, y);
        }
        __syncwarp();
        flush(tile * TILE + HTILE);
        __syncwarp();
    }

    // ---- tail: cols 96..100 consume h rows 95..99 ----
    {
        #pragma unroll
        for (int j = 0; j < TREM; ++j) {
            float ht = __ldg(h + (size_t)(NTILE * TILE - 1 + j) * BATCH_C
                             + block_b0 + tid);
            float xA = fmaf(A0, x, fmaf(A1, y, A4));
            float yA = fmaf(A2, x, fmaf(A3, y, A5));
            float xB = fmaf(B0, x, fmaf(B1, y, B4));
            float yB = fmaf(B2, x, fmaf(B3, y, B5));
            bool m = ht > p;
            x = m ? xB : xA;
            y = m ? yB : yA;
            so[j][tid] = make_float2(x, y);
        }
        __syncwarp();
        if (ttf < TREM) {
            float2* obase = out + (size_t)(block_b0 + wcol) * STRIDE
                          + NTILE * TILE + ttf;
            #pragma unroll
            for (int k = 0; k < 8; ++k)
                obase[(size_t)(4 * k) * STRIDE] = so[ttf][wcol + 4 * k];
        }
    }
}

// ---- generic fallback (any shape) ----
__global__ void ifs_generic(const float* __restrict__ coef,
                            const float* __restrict__ h,
                            float2* __restrict__ out,
                            int batch, int iters)
{
    int b = blockIdx.x * blockDim.x + threadIdx.x;
    if (b >= batch) return;
    const float4* c4 = reinterpret_cast<const float4*>(coef + (size_t)b * 12);
    float4 ca = c4[0], cb = c4[1], cc = c4[2];
    float A0=ca.x, A1=ca.y, A2=ca.z, A3=ca.w, A4=cb.x, A5=cb.y;
    float B0=cb.z, B1=cb.w, B2=cc.x, B3=cc.y, B4=cc.z, B5=cc.w;
    float j0 = fabsf(A0*A3 - A1*A2);
    float j1 = fabsf(B0*B3 - B1*B2);
    float p = j0 / (j0 + j1);
    float x = 0.05f, y = 0.05f;
    float2* o = out + (size_t)b * (iters + 1);
    o[0] = make_float2(x, y);
    for (int t = 0; t < iters; ++t) {
        float ht = __ldg(h + (size_t)t * batch + b);
        bool m = ht > p;
        float xn = fmaf(m?B0:A0, x, fmaf(m?B1:A1, y, m?B4:A4));
        float yn = fmaf(m?B2:A2, x, fmaf(m?B3:A3, y, m?B5:A5));
        x = xn; y = yn;
        o[t + 1] = make_float2(x, y);
    }
}

extern "C" void kernel_launch(void* const* d_in, const int* in_sizes, int n_in,
                              void* d_out, int out_size) {
    const float* coef = (const float*)d_in[0];
    const float* h    = (const float*)d_in[1];
    float2* out       = (float2*)d_out;

    int batch = in_sizes[0] / 12;
    int iters = in_sizes[1] / batch;

    if (batch == 200000 && iters == 100) {
        int blocks = (batch + BLOCK - 1) / BLOCK;
        ifs_spec<200000, 100><<<blocks, BLOCK>>>(coef, h, out);
    } else {
        int blocks = (batch + 255) / 256;
        ifs_generic<<<blocks, 256>>>(coef, h, out, batch, iters);
    }
}